// round 1
// baseline (speedup 1.0000x reference)
#include <cuda_runtime.h>
#include <cuda_bf16.h>
#include <math.h>

// ---------------- problem constants ----------------
#define BB    2
#define LL    8192
#define N2    16384      // 2*L, FFT length
#define LOG2N 14
#define DD    768
#define FF    768
#define ORDER 2
#define INNER 2304       // F*(ORDER+1)
#define NTH   512        // threads for FFT kernels
#define SMEM_FFT ((N2 + N2/2) * 8)   // 16384 float2 data + 8192 float2 twiddles = 196608 B

// ---------------- scratch (static device memory; no allocation) ----------------
__device__ float  d_h   [(size_t)ORDER * FF * N2];     // modulated filter, [o*F+f][p]
__device__ float2 d_hf  [(size_t)ORDER * FF * N2];     // filter spectrum (bitrev order, /n), [o*F+f][k]
__device__ float  d_proj[(size_t)BB * INNER * LL];     // in-proj output, transposed [b][c][l]
__device__ float  d_shrt[(size_t)BB * INNER * LL];     // after short conv, [b][c][l]
__device__ float  d_vout[(size_t)BB * FF * LL];        // final v, [b][f][l]

// ---------------- FFT helpers (in-place, radix-2, smem) ----------------
// forward: Gentleman-Sande DIF, natural -> bit-reversed order
__device__ __forceinline__ void fft_fwd(float2* data, const float2* tw, int tid) {
    for (int s = LOG2N - 1; s >= 0; s--) {
        int half = 1 << s;
        int tsh  = (LOG2N - 1) - s;
        #pragma unroll
        for (int q = 0; q < N2 / 2 / NTH; q++) {
            int t  = tid + (q * NTH);
            int j  = t & (half - 1);
            int i2 = ((t >> s) << (s + 1)) + j;
            float2 a = data[i2];
            float2 b = data[i2 + half];
            float2 w = tw[j << tsh];
            float dx = a.x - b.x, dy = a.y - b.y;
            data[i2]        = make_float2(a.x + b.x, a.y + b.y);
            data[i2 + half] = make_float2(dx * w.x - dy * w.y, dx * w.y + dy * w.x);
        }
        __syncthreads();
    }
}

// inverse: Cooley-Tukey DIT, bit-reversed -> natural order, UNNORMALIZED
__device__ __forceinline__ void fft_inv(float2* data, const float2* tw, int tid) {
    for (int s = 0; s < LOG2N; s++) {
        int half = 1 << s;
        int tsh  = (LOG2N - 1) - s;
        #pragma unroll
        for (int q = 0; q < N2 / 2 / NTH; q++) {
            int t  = tid + (q * NTH);
            int j  = t & (half - 1);
            int i2 = ((t >> s) << (s + 1)) + j;
            float2 a = data[i2];
            float2 b = data[i2 + half];
            float2 w = tw[j << tsh];           // conjugate for inverse
            float wy = -w.y;
            float bx = b.x * w.x - b.y * wy;
            float by = b.x * wy + b.y * w.x;
            data[i2]        = make_float2(a.x + bx, a.y + by);
            data[i2 + half] = make_float2(a.x - bx, a.y - by);
        }
        __syncthreads();
    }
}

__device__ __forceinline__ void build_twiddles(float2* tw, int tid) {
    for (int j = tid; j < N2 / 2; j += NTH) {
        // angle = -2*pi*j/N2  ->  sincospi with x = -j/8192 (exact in fp32)
        float x = -(float)j * (1.0f / 8192.0f);
        float s, c;
        sincospif(x, &s, &c);
        tw[j] = make_float2(c, s);
    }
}

// ---------------- kernel 1: filter MLP + modulation ----------------
// h[p, o*F+f] = (sin(t(p) @ w1 + b1) @ w2 + b2) * exp(-mod(p)*|decay[o,f]|)
// writes d_h[(o*F+f)*N2 + p]
__global__ __launch_bounds__(256) void hfilter_kernel(
    const float* __restrict__ w1, const float* __restrict__ b1,
    const float* __restrict__ w2, const float* __restrict__ b2,
    const float* __restrict__ decay)
{
    __shared__ float hid[16][64];
    const int p0  = blockIdx.x * 16;
    const int tid = threadIdx.x;

    // phase 1: hidden activations for 16 positions
    for (int idx = tid; idx < 16 * 64; idx += 256) {
        int pp = idx >> 6;
        int u  = idx & 63;
        int p  = p0 + pp;
        float off = (p < LL) ? (float)p : (float)(p - N2);
        float t[9];
        t[0] = off * (1.0f / 8192.0f);
        const float step = (8192.0f - 4.0f) / 3.0f;  // fp32, matches jnp.linspace
        #pragma unroll
        for (int i = 0; i < 4; i++) {
            float period = 4.0f + step * (float)i;
            float fr = 6.28318530717958647692f / period;  // fp32(2*pi)/period
            float ph = off * fr;                           // single fp32 mul (matches outer)
            t[1 + i] = cosf(ph);
            t[5 + i] = sinf(ph);
        }
        float a = b1[u];
        #pragma unroll
        for (int k = 0; k < 9; k++) a += t[k] * w1[k * 64 + u];
        hid[pp][u] = sinf(a);
    }
    __syncthreads();

    // phase 2: 1536 outputs, each thread handles 6 channels x 16 positions
    for (int oc = tid; oc < ORDER * FF; oc += 256) {
        float acc[16];
        float bv = b2[oc];
        #pragma unroll
        for (int pp = 0; pp < 16; pp++) acc[pp] = bv;
        for (int k = 0; k < 64; k++) {
            float wv = w2[k * (ORDER * FF) + oc];
            #pragma unroll
            for (int pp = 0; pp < 16; pp++) acc[pp] += hid[pp][k] * wv;
        }
        float dec = fabsf(decay[oc]);   // decay is [ORDER][F] row-major = oc
        float* dst = d_h + (size_t)oc * N2 + p0;
        #pragma unroll
        for (int pp = 0; pp < 16; pp++) {
            int p = p0 + pp;
            float mod = (p < LL) ? (float)p * (1.0f / 8191.0f)
                                 : (float)(N2 - 1 - p) * (1.0f / 8191.0f);
            dst[pp] = acc[pp] * expf(-mod * dec);
        }
    }
}

// ---------------- kernel 2: filter FFT (stores bitrev spectrum, pre-scaled 1/n) ----
__global__ __launch_bounds__(NTH) void hfft_kernel() {
    extern __shared__ float2 smem_f2[];
    float2* data = smem_f2;
    float2* tw   = smem_f2 + N2;
    const int ch  = blockIdx.x;        // o*F+f, 1536 blocks
    const int tid = threadIdx.x;

    build_twiddles(tw, tid);
    const float* src = d_h + (size_t)ch * N2;
    #pragma unroll
    for (int i = 0; i < N2 / NTH; i++) {
        int idx = tid + i * NTH;
        data[idx] = make_float2(src[idx], 0.0f);
    }
    __syncthreads();
    fft_fwd(data, tw, tid);
    const float scale = 1.0f / (float)N2;
    float2* dst = d_hf + (size_t)ch * N2;
    #pragma unroll
    for (int i = 0; i < N2 / NTH; i++) {
        int idx = tid + i * NTH;
        float2 a = data[idx];
        dst[idx] = make_float2(a.x * scale, a.y * scale);
    }
}

// ---------------- kernel 3: in-projection GEMM (output transposed [b][c][l]) ----
// C[b,c,l] = sum_d U[b,l,d] * W[d,c] + bias[c]
__global__ __launch_bounds__(256) void gemm_inproj(
    const float* __restrict__ U, const float* __restrict__ W,
    const float* __restrict__ bias)
{
    __shared__ float As[8][128];   // [k][m(l)]
    __shared__ float Bs[8][128];   // [k][n(c)]
    const int b  = blockIdx.z;
    const int c0 = blockIdx.x * 128;
    const int l0 = blockIdx.y * 128;
    const float* Ub = U + (size_t)b * LL * DD;
    float* Cb = d_proj + (size_t)b * INNER * LL;
    const int tid  = threadIdx.x;
    const int arow = tid >> 1, acol = (tid & 1) << 2;
    const int brow = tid >> 5, bcol = (tid & 31) << 2;
    const int m0 = (tid >> 4) << 3;
    const int n0 = (tid & 15) << 3;

    float acc[8][8];
    #pragma unroll
    for (int i = 0; i < 8; i++)
        #pragma unroll
        for (int j = 0; j < 8; j++) acc[i][j] = 0.0f;

    for (int k0 = 0; k0 < DD; k0 += 8) {
        float4 av = *(const float4*)(Ub + (size_t)(l0 + arow) * DD + k0 + acol);
        float4 bv = *(const float4*)(W + (size_t)(k0 + brow) * INNER + c0 + bcol);
        As[acol + 0][arow] = av.x;
        As[acol + 1][arow] = av.y;
        As[acol + 2][arow] = av.z;
        As[acol + 3][arow] = av.w;
        *(float4*)(&Bs[brow][bcol]) = bv;
        __syncthreads();
        #pragma unroll
        for (int k = 0; k < 8; k++) {
            float4 a0 = *(const float4*)&As[k][m0];
            float4 a1 = *(const float4*)&As[k][m0 + 4];
            float4 bb0 = *(const float4*)&Bs[k][n0];
            float4 bb1 = *(const float4*)&Bs[k][n0 + 4];
            float ra[8] = {a0.x, a0.y, a0.z, a0.w, a1.x, a1.y, a1.z, a1.w};
            float rb[8] = {bb0.x, bb0.y, bb0.z, bb0.w, bb1.x, bb1.y, bb1.z, bb1.w};
            #pragma unroll
            for (int i = 0; i < 8; i++)
                #pragma unroll
                for (int j = 0; j < 8; j++) acc[i][j] += ra[i] * rb[j];
        }
        __syncthreads();
    }
    #pragma unroll
    for (int j = 0; j < 8; j++) {
        float bb = bias[c0 + n0 + j];
        float* dst = Cb + (size_t)(c0 + n0 + j) * LL + l0 + m0;
        float4 o0 = make_float4(acc[0][j] + bb, acc[1][j] + bb, acc[2][j] + bb, acc[3][j] + bb);
        float4 o1 = make_float4(acc[4][j] + bb, acc[5][j] + bb, acc[6][j] + bb, acc[7][j] + bb);
        *(float4*)dst       = o0;
        *(float4*)(dst + 4) = o1;
    }
}

// ---------------- kernel 4: depthwise short conv (window 3, SAME) ----------------
__global__ __launch_bounds__(256) void shortconv_kernel(
    const float* __restrict__ w, const float* __restrict__ bias)
{
    const int b = blockIdx.z;
    const int c = blockIdx.y;
    const int l = blockIdx.x * 256 + threadIdx.x;
    const float* row = d_proj + ((size_t)b * INNER + c) * LL;
    float w0 = w[c], w1 = w[INNER + c], w2 = w[2 * INNER + c];
    float acc = bias[c] + w1 * row[l];
    if (l > 0)      acc += w0 * row[l - 1];
    if (l < LL - 1) acc += w2 * row[l + 1];
    d_shrt[((size_t)b * INNER + c) * LL + l] = acc;
}

// ---------------- kernel 5: fused FFT conv (both orders) ----------------
// per (b,f) channel: for o in 0..1: v = irfft(rfft(v)*Hf[o]) + v*bias[o]; v *= x[o]
__global__ __launch_bounds__(NTH) void fftconv_kernel(const float* __restrict__ bias) {
    extern __shared__ float2 smem_f2[];
    float2* data = smem_f2;
    float2* tw   = smem_f2 + N2;
    const int f   = blockIdx.x;   // 768
    const int b   = blockIdx.y;   // 2
    const int tid = threadIdx.x;

    build_twiddles(tw, tid);

    const float* vsrc = d_shrt + ((size_t)b * INNER + f) * LL;
    float v[LL / NTH];
    #pragma unroll
    for (int i = 0; i < LL / NTH; i++) v[i] = vsrc[tid + i * NTH];

    #pragma unroll 1
    for (int o = 0; o < ORDER; o++) {
        #pragma unroll
        for (int i = 0; i < LL / NTH; i++)
            data[tid + i * NTH] = make_float2(v[i], 0.0f);
        #pragma unroll
        for (int i = LL / NTH; i < N2 / NTH; i++)
            data[tid + i * NTH] = make_float2(0.0f, 0.0f);
        __syncthreads();

        fft_fwd(data, tw, tid);

        const float2* hf = d_hf + ((size_t)o * FF + f) * N2;
        #pragma unroll
        for (int i = 0; i < N2 / NTH; i++) {
            int idx = tid + i * NTH;
            float2 a = data[idx];
            float2 h = hf[idx];
            data[idx] = make_float2(a.x * h.x - a.y * h.y, a.x * h.y + a.y * h.x);
        }
        __syncthreads();

        fft_inv(data, tw, tid);

        float bs = bias[o * FF + f];
        const float* xsrc = d_shrt + ((size_t)b * INNER + (1 + o) * FF + f) * LL;
        #pragma unroll
        for (int i = 0; i < LL / NTH; i++) {
            int l = tid + i * NTH;
            float y = data[l].x;
            v[i] = (y + v[i] * bs) * xsrc[l];
        }
        __syncthreads();
    }
    float* dst = d_vout + ((size_t)b * FF + f) * LL;
    #pragma unroll
    for (int i = 0; i < LL / NTH; i++) dst[tid + i * NTH] = v[i];
}

// ---------------- kernel 6: output GEMM ----------------
// y[b,l,d] = sum_f V[b][f][l] * W[f,d] + bias[d]   (A read column-major from [f][l])
__global__ __launch_bounds__(256) void gemm_out(
    const float* __restrict__ W, const float* __restrict__ bias,
    float* __restrict__ Y)
{
    __shared__ float As[8][128];   // [k(f)][m(l)]
    __shared__ float Bs[8][128];   // [k(f)][n(d)]
    const int b  = blockIdx.z;
    const int d0 = blockIdx.x * 128;
    const int l0 = blockIdx.y * 128;
    const float* Vb = d_vout + (size_t)b * FF * LL;
    float* Yb = Y + (size_t)b * LL * DD;
    const int tid   = threadIdx.x;
    const int akrow = tid >> 5, amcol = (tid & 31) << 2;
    const int brow  = tid >> 5, bcol  = (tid & 31) << 2;
    const int m0 = (tid >> 4) << 3;
    const int n0 = (tid & 15) << 3;

    float acc[8][8];
    #pragma unroll
    for (int i = 0; i < 8; i++)
        #pragma unroll
        for (int j = 0; j < 8; j++) acc[i][j] = 0.0f;

    for (int k0 = 0; k0 < FF; k0 += 8) {
        float4 av = *(const float4*)(Vb + (size_t)(k0 + akrow) * LL + l0 + amcol);
        float4 bv = *(const float4*)(W + (size_t)(k0 + brow) * DD + d0 + bcol);
        *(float4*)(&As[akrow][amcol]) = av;
        *(float4*)(&Bs[brow][bcol])   = bv;
        __syncthreads();
        #pragma unroll
        for (int k = 0; k < 8; k++) {
            float4 a0 = *(const float4*)&As[k][m0];
            float4 a1 = *(const float4*)&As[k][m0 + 4];
            float4 bb0 = *(const float4*)&Bs[k][n0];
            float4 bb1 = *(const float4*)&Bs[k][n0 + 4];
            float ra[8] = {a0.x, a0.y, a0.z, a0.w, a1.x, a1.y, a1.z, a1.w};
            float rb[8] = {bb0.x, bb0.y, bb0.z, bb0.w, bb1.x, bb1.y, bb1.z, bb1.w};
            #pragma unroll
            for (int i = 0; i < 8; i++)
                #pragma unroll
                for (int j = 0; j < 8; j++) acc[i][j] += ra[i] * rb[j];
        }
        __syncthreads();
    }
    #pragma unroll
    for (int i = 0; i < 8; i++) {
        float* dst = Yb + (size_t)(l0 + m0 + i) * DD + d0 + n0;
        float4 o0 = make_float4(acc[i][0] + bias[d0 + n0 + 0],
                                acc[i][1] + bias[d0 + n0 + 1],
                                acc[i][2] + bias[d0 + n0 + 2],
                                acc[i][3] + bias[d0 + n0 + 3]);
        float4 o1 = make_float4(acc[i][4] + bias[d0 + n0 + 4],
                                acc[i][5] + bias[d0 + n0 + 5],
                                acc[i][6] + bias[d0 + n0 + 6],
                                acc[i][7] + bias[d0 + n0 + 7]);
        *(float4*)dst       = o0;
        *(float4*)(dst + 4) = o1;
    }
}

// ---------------- launch ----------------
extern "C" void kernel_launch(void* const* d_in, const int* in_sizes, int n_in,
                              void* d_out, int out_size) {
    const float* u     = (const float*)d_in[0];
    const float* fw1   = (const float*)d_in[1];
    const float* fb1   = (const float*)d_in[2];
    const float* fw2   = (const float*)d_in[3];
    const float* fb2   = (const float*)d_in[4];
    const float* decay = (const float*)d_in[5];
    const float* bias  = (const float*)d_in[6];
    const float* ipw   = (const float*)d_in[7];
    const float* ipb   = (const float*)d_in[8];
    const float* sw    = (const float*)d_in[9];
    const float* sb    = (const float*)d_in[10];
    const float* ow    = (const float*)d_in[11];
    const float* ob    = (const float*)d_in[12];
    float* y = (float*)d_out;

    cudaFuncSetAttribute(hfft_kernel,    cudaFuncAttributeMaxDynamicSharedMemorySize, SMEM_FFT);
    cudaFuncSetAttribute(fftconv_kernel, cudaFuncAttributeMaxDynamicSharedMemorySize, SMEM_FFT);

    hfilter_kernel<<<N2 / 16, 256>>>(fw1, fb1, fw2, fb2, decay);
    hfft_kernel<<<ORDER * FF, NTH, SMEM_FFT>>>();
    gemm_inproj<<<dim3(INNER / 128, LL / 128, BB), 256>>>(u, ipw, ipb);
    shortconv_kernel<<<dim3(LL / 256, INNER, BB), 256>>>(sw, sb);
    fftconv_kernel<<<dim3(FF, BB), NTH, SMEM_FFT>>>(bias);
    gemm_out<<<dim3(DD / 128, LL / 128, BB), 256>>>(ow, ob, y);
}

// round 3
// speedup vs baseline: 1.3588x; 1.3588x over previous
#include <cuda_runtime.h>
#include <cuda_bf16.h>
#include <math.h>

// ---------------- problem constants ----------------
#define BB    2
#define LL    8192
#define N2    16384      // 2*L, FFT length
#define LOG2N 14
#define DD    768
#define FF    768
#define ORDER 2
#define INNER 2304       // F*(ORDER+1)
#define NPAIR 384        // FF/2 channel pairs
#define NTH   512        // threads for FFT kernels
#define SMEM_FFT ((N2 + N2/2) * 8)   // 16384 float2 data + 8192 float2 twiddles = 196608 B

// ---------------- scratch (static device memory; no allocation) ----------------
__device__ float2 d_h2 [(size_t)ORDER * NPAIR * N2];        // filter pairs: .x = ch 2i, .y = ch 2i+1
__device__ float2 d_hf [(size_t)ORDER * NPAIR * 2 * N2];    // spectra [o][pair][ch][p] bitrev, /n
__device__ float  d_proj[(size_t)BB * INNER * LL];          // in-proj output, [b][c][l]
__device__ float  d_vout[(size_t)BB * FF * LL];             // final v, [b][f][l]

// ---------------- FFT helpers (in-place, radix-2, smem) ----------------
// forward: Gentleman-Sande DIF, natural -> bit-reversed order
__device__ __forceinline__ void fft_fwd(float2* data, const float2* tw, int tid) {
    for (int s = LOG2N - 1; s >= 0; s--) {
        int half = 1 << s;
        int tsh  = (LOG2N - 1) - s;
        #pragma unroll
        for (int q = 0; q < N2 / 2 / NTH; q++) {
            int t  = tid + (q * NTH);
            int j  = t & (half - 1);
            int i2 = ((t >> s) << (s + 1)) + j;
            float2 a = data[i2];
            float2 b = data[i2 + half];
            float2 w = tw[j << tsh];
            float dx = a.x - b.x, dy = a.y - b.y;
            data[i2]        = make_float2(a.x + b.x, a.y + b.y);
            data[i2 + half] = make_float2(dx * w.x - dy * w.y, dx * w.y + dy * w.x);
        }
        __syncthreads();
    }
}

// inverse: Cooley-Tukey DIT, bit-reversed -> natural order, UNNORMALIZED
__device__ __forceinline__ void fft_inv(float2* data, const float2* tw, int tid) {
    for (int s = 0; s < LOG2N; s++) {
        int half = 1 << s;
        int tsh  = (LOG2N - 1) - s;
        #pragma unroll
        for (int q = 0; q < N2 / 2 / NTH; q++) {
            int t  = tid + (q * NTH);
            int j  = t & (half - 1);
            int i2 = ((t >> s) << (s + 1)) + j;
            float2 a = data[i2];
            float2 b = data[i2 + half];
            float2 w = tw[j << tsh];           // conjugate for inverse
            float wy = -w.y;
            float bx = b.x * w.x - b.y * wy;
            float by = b.x * wy + b.y * w.x;
            data[i2]        = make_float2(a.x + bx, a.y + by);
            data[i2 + half] = make_float2(a.x - bx, a.y - by);
        }
        __syncthreads();
    }
}

__device__ __forceinline__ void build_twiddles(float2* tw, int tid) {
    for (int j = tid; j < N2 / 2; j += NTH) {
        float x = -(float)j * (1.0f / 8192.0f);
        float s, c;
        sincospif(x, &s, &c);
        tw[j] = make_float2(c, s);
    }
}

__device__ __forceinline__ int rev14(int p) {
    return (int)(__brev((unsigned)p) >> 18);
}

// fused depthwise short conv (window 3, SAME), row fully resident in gmem
__device__ __forceinline__ float scval(const float* __restrict__ row, int l,
                                       float w0, float w1, float w2, float bb) {
    float acc = bb + w1 * row[l];
    if (l > 0)      acc += w0 * row[l - 1];
    if (l < LL - 1) acc += w2 * row[l + 1];
    return acc;
}

// ---------------- kernel 1: filter MLP + modulation (pair-interleaved output) ----
__global__ __launch_bounds__(256) void hfilter_kernel(
    const float* __restrict__ w1, const float* __restrict__ b1,
    const float* __restrict__ w2, const float* __restrict__ b2,
    const float* __restrict__ decay)
{
    __shared__ float hid[16][64];
    const int p0  = blockIdx.x * 16;
    const int tid = threadIdx.x;

    for (int idx = tid; idx < 16 * 64; idx += 256) {
        int pp = idx >> 6;
        int u  = idx & 63;
        int p  = p0 + pp;
        float off = (p < LL) ? (float)p : (float)(p - N2);
        float t[9];
        t[0] = off * (1.0f / 8192.0f);
        const float step = (8192.0f - 4.0f) / 3.0f;
        #pragma unroll
        for (int i = 0; i < 4; i++) {
            float period = 4.0f + step * (float)i;
            float fr = 6.28318530717958647692f / period;
            float ph = off * fr;
            t[1 + i] = cosf(ph);
            t[5 + i] = sinf(ph);
        }
        float a = b1[u];
        #pragma unroll
        for (int k = 0; k < 9; k++) a += t[k] * w1[k * 64 + u];
        hid[pp][u] = sinf(a);
    }
    __syncthreads();

    for (int oc = tid; oc < ORDER * FF; oc += 256) {
        float acc[16];
        float bv = b2[oc];
        #pragma unroll
        for (int pp = 0; pp < 16; pp++) acc[pp] = bv;
        for (int k = 0; k < 64; k++) {
            float wv = w2[k * (ORDER * FF) + oc];
            #pragma unroll
            for (int pp = 0; pp < 16; pp++) acc[pp] += hid[pp][k] * wv;
        }
        float dec = fabsf(decay[oc]);
        int o = oc / FF, f = oc - o * FF;
        float* dst = (float*)(d_h2 + ((size_t)(o * NPAIR + (f >> 1))) * N2 + p0) + (f & 1);
        #pragma unroll
        for (int pp = 0; pp < 16; pp++) {
            int p = p0 + pp;
            float mod = (p < LL) ? (float)p * (1.0f / 8191.0f)
                                 : (float)(N2 - 1 - p) * (1.0f / 8191.0f);
            dst[2 * pp] = acc[pp] * expf(-mod * dec);
        }
    }
}

// ---------------- kernel 2: paired filter FFT (2 real channels per complex FFT) ----
__global__ __launch_bounds__(NTH) void hfft_kernel() {
    extern __shared__ float2 smem_f2[];
    float2* data = smem_f2;
    float2* tw   = smem_f2 + N2;
    const int cp  = blockIdx.x;        // o*NPAIR + pair, 768 blocks
    const int tid = threadIdx.x;

    build_twiddles(tw, tid);
    const float2* src = d_h2 + (size_t)cp * N2;
    #pragma unroll
    for (int i = 0; i < N2 / NTH; i++) {
        int idx = tid + i * NTH;
        data[idx] = src[idx];            // z = h0 + i*h1
    }
    __syncthreads();
    fft_fwd(data, tw, tid);

    // unpack two Hermitian spectra in bit-reversed domain, scale by 1/n
    const float s = 0.5f / (float)N2;
    float2* hf0 = d_hf + (size_t)(cp * 2 + 0) * N2;
    float2* hf1 = d_hf + (size_t)(cp * 2 + 1) * N2;
    #pragma unroll
    for (int i = 0; i < N2 / NTH; i++) {
        int p  = tid + i * NTH;
        int k  = rev14(p);
        int km = (N2 - k) & (N2 - 1);
        int pm = rev14(km);
        if (p <= pm) {
            float2 z1 = data[p];
            float2 z2 = data[pm];
            float2 H0 = make_float2(s * (z1.x + z2.x),  s * (z1.y - z2.y));
            float2 H1 = make_float2(s * (z1.y + z2.y), -s * (z1.x - z2.x));
            hf0[p]  = H0;
            hf1[p]  = H1;
            hf0[pm] = make_float2(H0.x, -H0.y);
            hf1[pm] = make_float2(H1.x, -H1.y);
        }
    }
}

// ---------------- kernel 3: in-projection GEMM (output transposed [b][c][l]) ----
__global__ __launch_bounds__(256) void gemm_inproj(
    const float* __restrict__ U, const float* __restrict__ W,
    const float* __restrict__ bias)
{
    __shared__ float As[8][128];
    __shared__ float Bs[8][128];
    const int b  = blockIdx.z;
    const int c0 = blockIdx.x * 128;
    const int l0 = blockIdx.y * 128;
    const float* Ub = U + (size_t)b * LL * DD;
    float* Cb = d_proj + (size_t)b * INNER * LL;
    const int tid  = threadIdx.x;
    const int arow = tid >> 1, acol = (tid & 1) << 2;
    const int brow = tid >> 5, bcol = (tid & 31) << 2;
    const int m0 = (tid >> 4) << 3;
    const int n0 = (tid & 15) << 3;

    float acc[8][8];
    #pragma unroll
    for (int i = 0; i < 8; i++)
        #pragma unroll
        for (int j = 0; j < 8; j++) acc[i][j] = 0.0f;

    for (int k0 = 0; k0 < DD; k0 += 8) {
        float4 av = *(const float4*)(Ub + (size_t)(l0 + arow) * DD + k0 + acol);
        float4 bv = *(const float4*)(W + (size_t)(k0 + brow) * INNER + c0 + bcol);
        As[acol + 0][arow] = av.x;
        As[acol + 1][arow] = av.y;
        As[acol + 2][arow] = av.z;
        As[acol + 3][arow] = av.w;
        *(float4*)(&Bs[brow][bcol]) = bv;
        __syncthreads();
        #pragma unroll
        for (int k = 0; k < 8; k++) {
            float4 a0 = *(const float4*)&As[k][m0];
            float4 a1 = *(const float4*)&As[k][m0 + 4];
            float4 bb0 = *(const float4*)&Bs[k][n0];
            float4 bb1 = *(const float4*)&Bs[k][n0 + 4];
            float ra[8] = {a0.x, a0.y, a0.z, a0.w, a1.x, a1.y, a1.z, a1.w};
            float rb[8] = {bb0.x, bb0.y, bb0.z, bb0.w, bb1.x, bb1.y, bb1.z, bb1.w};
            #pragma unroll
            for (int i = 0; i < 8; i++)
                #pragma unroll
                for (int j = 0; j < 8; j++) acc[i][j] += ra[i] * rb[j];
        }
        __syncthreads();
    }
    #pragma unroll
    for (int j = 0; j < 8; j++) {
        float bb = bias[c0 + n0 + j];
        float* dst = Cb + (size_t)(c0 + n0 + j) * LL + l0 + m0;
        float4 o0 = make_float4(acc[0][j] + bb, acc[1][j] + bb, acc[2][j] + bb, acc[3][j] + bb);
        float4 o1 = make_float4(acc[4][j] + bb, acc[5][j] + bb, acc[6][j] + bb, acc[7][j] + bb);
        *(float4*)dst       = o0;
        *(float4*)(dst + 4) = o1;
    }
}

// ---------------- kernel 4: fused FFT conv (2 channels per block, both orders,
//                  short conv fused into loads) ----------------
__global__ __launch_bounds__(NTH) void fftconv_kernel(
    const float* __restrict__ bias,
    const float* __restrict__ sw, const float* __restrict__ sb)
{
    extern __shared__ float2 smem_f2[];
    float2* data = smem_f2;
    float2* tw   = smem_f2 + N2;
    const int pr  = blockIdx.x;   // pair index, 384
    const int b   = blockIdx.y;   // 2
    const int tid = threadIdx.x;
    const int f0  = 2 * pr;
    const int f1  = 2 * pr + 1;

    build_twiddles(tw, tid);

    // v = shortconv(proj row f), fused
    float v0[LL / NTH], v1[LL / NTH];
    {
        const float* r0 = d_proj + ((size_t)b * INNER + f0) * LL;
        const float* r1 = d_proj + ((size_t)b * INNER + f1) * LL;
        float a0 = sw[f0], a1 = sw[INNER + f0], a2 = sw[2 * INNER + f0], ab = sb[f0];
        float c0 = sw[f1], c1 = sw[INNER + f1], c2 = sw[2 * INNER + f1], cb = sb[f1];
        #pragma unroll
        for (int i = 0; i < LL / NTH; i++) {
            int l = tid + i * NTH;
            v0[i] = scval(r0, l, a0, a1, a2, ab);
            v1[i] = scval(r1, l, c0, c1, c2, cb);
        }
    }

    #pragma unroll 1
    for (int o = 0; o < ORDER; o++) {
        #pragma unroll
        for (int i = 0; i < LL / NTH; i++)
            data[tid + i * NTH] = make_float2(v0[i], v1[i]);
        #pragma unroll
        for (int i = LL / NTH; i < N2 / NTH; i++)
            data[tid + i * NTH] = make_float2(0.0f, 0.0f);
        __syncthreads();

        fft_fwd(data, tw, tid);

        // paired Hermitian unpack, per-channel filter multiply, repack (bitrev domain)
        const float2* hf0 = d_hf + (size_t)((o * NPAIR + pr) * 2 + 0) * N2;
        const float2* hf1 = d_hf + (size_t)((o * NPAIR + pr) * 2 + 1) * N2;
        #pragma unroll
        for (int i = 0; i < N2 / NTH; i++) {
            int p  = tid + i * NTH;
            int k  = rev14(p);
            int km = (N2 - k) & (N2 - 1);
            int pm = rev14(km);
            if (p <= pm) {
                float2 z1 = data[p];
                float2 z2 = data[pm];
                float2 V0 = make_float2(0.5f * (z1.x + z2.x),  0.5f * (z1.y - z2.y));
                float2 V1 = make_float2(0.5f * (z1.y + z2.y), -0.5f * (z1.x - z2.x));
                float2 H0 = hf0[p];
                float2 H1 = hf1[p];
                float2 Y0 = make_float2(V0.x * H0.x - V0.y * H0.y, V0.x * H0.y + V0.y * H0.x);
                float2 Y1 = make_float2(V1.x * H1.x - V1.y * H1.y, V1.x * H1.y + V1.y * H1.x);
                data[p]  = make_float2(Y0.x - Y1.y, Y0.y + Y1.x);
                data[pm] = make_float2(Y0.x + Y1.y, Y1.x - Y0.y);
            }
        }
        __syncthreads();

        fft_inv(data, tw, tid);

        // v = (y + v*bias) * gate  (gate = shortconv of proj row (1+o)*F + f)
        float bs0 = bias[o * FF + f0];
        float bs1 = bias[o * FF + f1];
        const int g0c = (1 + o) * FF + f0;
        const int g1c = (1 + o) * FF + f1;
        const float* g0r = d_proj + ((size_t)b * INNER + g0c) * LL;
        const float* g1r = d_proj + ((size_t)b * INNER + g1c) * LL;
        float ga0 = sw[g0c], ga1 = sw[INNER + g0c], ga2 = sw[2 * INNER + g0c], gab = sb[g0c];
        float gc0 = sw[g1c], gc1 = sw[INNER + g1c], gc2 = sw[2 * INNER + g1c], gcb = sb[g1c];
        #pragma unroll
        for (int i = 0; i < LL / NTH; i++) {
            int l = tid + i * NTH;
            float2 y = data[l];
            float g0 = scval(g0r, l, ga0, ga1, ga2, gab);
            float g1 = scval(g1r, l, gc0, gc1, gc2, gcb);
            v0[i] = (y.x + v0[i] * bs0) * g0;
            v1[i] = (y.y + v1[i] * bs1) * g1;
        }
        __syncthreads();
    }
    float* dst0 = d_vout + ((size_t)b * FF + f0) * LL;
    float* dst1 = d_vout + ((size_t)b * FF + f1) * LL;
    #pragma unroll
    for (int i = 0; i < LL / NTH; i++) {
        dst0[tid + i * NTH] = v0[i];
        dst1[tid + i * NTH] = v1[i];
    }
}

// ---------------- kernel 5: output GEMM ----------------
__global__ __launch_bounds__(256) void gemm_out(
    const float* __restrict__ W, const float* __restrict__ bias,
    float* __restrict__ Y)
{
    __shared__ float As[8][128];
    __shared__ float Bs[8][128];
    const int b  = blockIdx.z;
    const int d0 = blockIdx.x * 128;
    const int l0 = blockIdx.y * 128;
    const float* Vb = d_vout + (size_t)b * FF * LL;
    float* Yb = Y + (size_t)b * LL * DD;
    const int tid   = threadIdx.x;
    const int akrow = tid >> 5, amcol = (tid & 31) << 2;
    const int brow  = tid >> 5, bcol  = (tid & 31) << 2;
    const int m0 = (tid >> 4) << 3;
    const int n0 = (tid & 15) << 3;

    float acc[8][8];
    #pragma unroll
    for (int i = 0; i < 8; i++)
        #pragma unroll
        for (int j = 0; j < 8; j++) acc[i][j] = 0.0f;

    for (int k0 = 0; k0 < FF; k0 += 8) {
        float4 av = *(const float4*)(Vb + (size_t)(k0 + akrow) * LL + l0 + amcol);
        float4 bv = *(const float4*)(W + (size_t)(k0 + brow) * DD + d0 + bcol);
        *(float4*)(&As[akrow][amcol]) = av;
        *(float4*)(&Bs[brow][bcol])   = bv;
        __syncthreads();
        #pragma unroll
        for (int k = 0; k < 8; k++) {
            float4 a0 = *(const float4*)&As[k][m0];
            float4 a1 = *(const float4*)&As[k][m0 + 4];
            float4 bb0 = *(const float4*)&Bs[k][n0];
            float4 bb1 = *(const float4*)&Bs[k][n0 + 4];
            float ra[8] = {a0.x, a0.y, a0.z, a0.w, a1.x, a1.y, a1.z, a1.w};
            float rb[8] = {bb0.x, bb0.y, bb0.z, bb0.w, bb1.x, bb1.y, bb1.z, bb1.w};
            #pragma unroll
            for (int i = 0; i < 8; i++)
                #pragma unroll
                for (int j = 0; j < 8; j++) acc[i][j] += ra[i] * rb[j];
        }
        __syncthreads();
    }
    #pragma unroll
    for (int i = 0; i < 8; i++) {
        float* dst = Yb + (size_t)(l0 + m0 + i) * DD + d0 + n0;
        float4 o0 = make_float4(acc[i][0] + bias[d0 + n0 + 0],
                                acc[i][1] + bias[d0 + n0 + 1],
                                acc[i][2] + bias[d0 + n0 + 2],
                                acc[i][3] + bias[d0 + n0 + 3]);
        float4 o1 = make_float4(acc[i][4] + bias[d0 + n0 + 4],
                                acc[i][5] + bias[d0 + n0 + 5],
                                acc[i][6] + bias[d0 + n0 + 6],
                                acc[i][7] + bias[d0 + n0 + 7]);
        *(float4*)dst       = o0;
        *(float4*)(dst + 4) = o1;
    }
}

// ---------------- launch ----------------
extern "C" void kernel_launch(void* const* d_in, const int* in_sizes, int n_in,
                              void* d_out, int out_size) {
    const float* u     = (const float*)d_in[0];
    const float* fw1   = (const float*)d_in[1];
    const float* fb1   = (const float*)d_in[2];
    const float* fw2   = (const float*)d_in[3];
    const float* fb2   = (const float*)d_in[4];
    const float* decay = (const float*)d_in[5];
    const float* bias  = (const float*)d_in[6];
    const float* ipw   = (const float*)d_in[7];
    const float* ipb   = (const float*)d_in[8];
    const float* sw    = (const float*)d_in[9];
    const float* sb    = (const float*)d_in[10];
    const float* ow    = (const float*)d_in[11];
    const float* ob    = (const float*)d_in[12];
    float* y = (float*)d_out;

    cudaFuncSetAttribute(hfft_kernel,    cudaFuncAttributeMaxDynamicSharedMemorySize, SMEM_FFT);
    cudaFuncSetAttribute(fftconv_kernel, cudaFuncAttributeMaxDynamicSharedMemorySize, SMEM_FFT);

    hfilter_kernel<<<N2 / 16, 256>>>(fw1, fb1, fw2, fb2, decay);
    hfft_kernel<<<ORDER * NPAIR, NTH, SMEM_FFT>>>();
    gemm_inproj<<<dim3(INNER / 128, LL / 128, BB), 256>>>(u, ipw, ipb);
    fftconv_kernel<<<dim3(NPAIR, BB), NTH, SMEM_FFT>>>(bias, sw, sb);
    gemm_out<<<dim3(DD / 128, LL / 128, BB), 256>>>(ow, ob, y);
}

// round 5
// speedup vs baseline: 1.4803x; 1.0894x over previous
#include <cuda_runtime.h>
#include <cuda_bf16.h>
#include <math.h>
#include <stdint.h>

// ---------------- problem constants ----------------
#define BB    2
#define LL    8192
#define N2    16384      // 2*L, FFT length
#define LOG2N 14
#define DD    768
#define FF    768
#define ORDER 2
#define INNER 2304       // F*(ORDER+1)
#define NPAIR 384        // FF/2 channel pairs
#define NTH   512        // threads for FFT kernels
#define SMEM_FFT ((N2 + N2/2) * 8)   // 16384 float2 data + 8192 float2 twiddles = 196608 B

// ---------------- scratch (static device memory; no allocation) ----------------
__device__ float2 d_h2 [(size_t)ORDER * NPAIR * N2];        // filter pairs: .x = ch 2i, .y = ch 2i+1
__device__ float2 d_hf [(size_t)ORDER * NPAIR * 2 * N2];    // spectra [o][pair][ch][p] bitrev, /n
__device__ float  d_proj[(size_t)BB * INNER * LL];          // in-proj output, [b][c][l]
__device__ float  d_vout[(size_t)BB * FF * LL];             // final v, [b][f][l]

// ---------------- FFT helpers (in-place, radix-2, smem) ----------------
__device__ __forceinline__ void fft_fwd(float2* data, const float2* tw, int tid) {
    for (int s = LOG2N - 1; s >= 0; s--) {
        int half = 1 << s;
        int tsh  = (LOG2N - 1) - s;
        #pragma unroll
        for (int q = 0; q < N2 / 2 / NTH; q++) {
            int t  = tid + (q * NTH);
            int j  = t & (half - 1);
            int i2 = ((t >> s) << (s + 1)) + j;
            float2 a = data[i2];
            float2 b = data[i2 + half];
            float2 w = tw[j << tsh];
            float dx = a.x - b.x, dy = a.y - b.y;
            data[i2]        = make_float2(a.x + b.x, a.y + b.y);
            data[i2 + half] = make_float2(dx * w.x - dy * w.y, dx * w.y + dy * w.x);
        }
        __syncthreads();
    }
}

__device__ __forceinline__ void fft_inv(float2* data, const float2* tw, int tid) {
    for (int s = 0; s < LOG2N; s++) {
        int half = 1 << s;
        int tsh  = (LOG2N - 1) - s;
        #pragma unroll
        for (int q = 0; q < N2 / 2 / NTH; q++) {
            int t  = tid + (q * NTH);
            int j  = t & (half - 1);
            int i2 = ((t >> s) << (s + 1)) + j;
            float2 a = data[i2];
            float2 b = data[i2 + half];
            float2 w = tw[j << tsh];
            float wy = -w.y;
            float bx = b.x * w.x - b.y * wy;
            float by = b.x * wy + b.y * w.x;
            data[i2]        = make_float2(a.x + bx, a.y + by);
            data[i2 + half] = make_float2(a.x - bx, a.y - by);
        }
        __syncthreads();
    }
}

__device__ __forceinline__ void build_twiddles(float2* tw, int tid) {
    for (int j = tid; j < N2 / 2; j += NTH) {
        float x = -(float)j * (1.0f / 8192.0f);
        float s, c;
        sincospif(x, &s, &c);
        tw[j] = make_float2(c, s);
    }
}

__device__ __forceinline__ int rev14(int p) {
    return (int)(__brev((unsigned)p) >> 18);
}

__device__ __forceinline__ float scval(const float* __restrict__ row, int l,
                                       float w0, float w1, float w2, float bb) {
    float acc = bb + w1 * row[l];
    if (l > 0)      acc += w0 * row[l - 1];
    if (l < LL - 1) acc += w2 * row[l + 1];
    return acc;
}

// ---------------- tf32x3 MMA helpers ----------------
__device__ __forceinline__ void split_tf32(float x, uint32_t& hi, uint32_t& lo) {
    uint32_t xb = __float_as_uint(x);
    hi = xb & 0xFFFFE000u;
    float lof = x - __uint_as_float(hi);
    lo = __float_as_uint(lof) & 0xFFFFE000u;
}

__device__ __forceinline__ void mma_tf32(float* c, const uint32_t* a, const uint32_t* b) {
    asm volatile(
        "mma.sync.aligned.m16n8k8.row.col.f32.tf32.tf32.f32 "
        "{%0,%1,%2,%3}, {%4,%5,%6,%7}, {%8,%9}, {%0,%1,%2,%3};"
        : "+f"(c[0]), "+f"(c[1]), "+f"(c[2]), "+f"(c[3])
        : "r"(a[0]), "r"(a[1]), "r"(a[2]), "r"(a[3]), "r"(b[0]), "r"(b[1]));
}

// ---------------- kernel 1: filter MLP + modulation (pair-interleaved output) ----
__global__ __launch_bounds__(256) void hfilter_kernel(
    const float* __restrict__ w1, const float* __restrict__ b1,
    const float* __restrict__ w2, const float* __restrict__ b2,
    const float* __restrict__ decay)
{
    __shared__ float hid[16][64];
    const int p0  = blockIdx.x * 16;
    const int tid = threadIdx.x;

    for (int idx = tid; idx < 16 * 64; idx += 256) {
        int pp = idx >> 6;
        int u  = idx & 63;
        int p  = p0 + pp;
        float off = (p < LL) ? (float)p : (float)(p - N2);
        float t[9];
        t[0] = off * (1.0f / 8192.0f);
        const float step = (8192.0f - 4.0f) / 3.0f;
        #pragma unroll
        for (int i = 0; i < 4; i++) {
            float period = 4.0f + step * (float)i;
            float fr = 6.28318530717958647692f / period;
            float ph = off * fr;
            t[1 + i] = cosf(ph);
            t[5 + i] = sinf(ph);
        }
        float a = b1[u];
        #pragma unroll
        for (int k = 0; k < 9; k++) a += t[k] * w1[k * 64 + u];
        hid[pp][u] = sinf(a);
    }
    __syncthreads();

    for (int oc = tid; oc < ORDER * FF; oc += 256) {
        float acc[16];
        float bv = b2[oc];
        #pragma unroll
        for (int pp = 0; pp < 16; pp++) acc[pp] = bv;
        for (int k = 0; k < 64; k++) {
            float wv = w2[k * (ORDER * FF) + oc];
            #pragma unroll
            for (int pp = 0; pp < 16; pp++) acc[pp] += hid[pp][k] * wv;
        }
        float dec = fabsf(decay[oc]);
        int o = oc / FF, f = oc - o * FF;
        float* dst = (float*)(d_h2 + ((size_t)(o * NPAIR + (f >> 1))) * N2 + p0) + (f & 1);
        #pragma unroll
        for (int pp = 0; pp < 16; pp++) {
            int p = p0 + pp;
            float mod = (p < LL) ? (float)p * (1.0f / 8191.0f)
                                 : (float)(N2 - 1 - p) * (1.0f / 8191.0f);
            dst[2 * pp] = acc[pp] * expf(-mod * dec);
        }
    }
}

// ---------------- kernel 2: paired filter FFT ----------------
__global__ __launch_bounds__(NTH) void hfft_kernel() {
    extern __shared__ float2 smem_f2[];
    float2* data = smem_f2;
    float2* tw   = smem_f2 + N2;
    const int cp  = blockIdx.x;
    const int tid = threadIdx.x;

    build_twiddles(tw, tid);
    const float2* src = d_h2 + (size_t)cp * N2;
    #pragma unroll
    for (int i = 0; i < N2 / NTH; i++) {
        int idx = tid + i * NTH;
        data[idx] = src[idx];
    }
    __syncthreads();
    fft_fwd(data, tw, tid);

    const float s = 0.5f / (float)N2;
    float2* hf0 = d_hf + (size_t)(cp * 2 + 0) * N2;
    float2* hf1 = d_hf + (size_t)(cp * 2 + 1) * N2;
    #pragma unroll
    for (int i = 0; i < N2 / NTH; i++) {
        int p  = tid + i * NTH;
        int k  = rev14(p);
        int km = (N2 - k) & (N2 - 1);
        int pm = rev14(km);
        if (p <= pm) {
            float2 z1 = data[p];
            float2 z2 = data[pm];
            float2 H0 = make_float2(s * (z1.x + z2.x),  s * (z1.y - z2.y));
            float2 H1 = make_float2(s * (z1.y + z2.y), -s * (z1.x - z2.x));
            hf0[p]  = H0;
            hf1[p]  = H1;
            hf0[pm] = make_float2(H0.x, -H0.y);
            hf1[pm] = make_float2(H1.x, -H1.y);
        }
    }
}

// ---------------- kernel 3: in-projection GEMM, tf32x3 tensor cores ----------------
// C[b,c,l] = sum_d U[b,l,d]*W[d,c] + bias[c]  (output transposed [c][l])
__global__ __launch_bounds__(256) void gemm_inproj_tc(
    const float* __restrict__ U, const float* __restrict__ W,
    const float* __restrict__ bias)
{
    __shared__ float As[32][132];   // [k][m(l)]
    __shared__ float Bs[32][132];   // [k][n(c)]
    const int b  = blockIdx.z;
    const int c0 = blockIdx.x * 128;
    const int l0 = blockIdx.y * 128;
    const float* Ub = U + (size_t)b * LL * DD;
    float* Cb = d_proj + (size_t)b * INNER * LL;

    const int tid    = threadIdx.x;
    const int wid    = tid >> 5;
    const int lane   = tid & 31;
    const int warp_m = wid >> 2;    // 0..1
    const int warp_n = wid & 3;     // 0..3
    const int q      = lane >> 2;   // 0..7
    const int r      = lane & 3;    // 0..3

    float acc[4][4][4];
    #pragma unroll
    for (int mt = 0; mt < 4; mt++)
        #pragma unroll
        for (int nt = 0; nt < 4; nt++)
            #pragma unroll
            for (int j = 0; j < 4; j++) acc[mt][nt][j] = 0.0f;

    for (int k0 = 0; k0 < DD; k0 += 32) {
        #pragma unroll
        for (int i = 0; i < 4; i++) {
            int slot = tid + i * 256;
            // A: row-major [l][d] — float4 along k
            int m  = slot >> 3;
            int kq = (slot & 7) * 4;
            float4 v = *(const float4*)(Ub + (size_t)(l0 + m) * DD + k0 + kq);
            As[kq + 0][m] = v.x;
            As[kq + 1][m] = v.y;
            As[kq + 2][m] = v.z;
            As[kq + 3][m] = v.w;
            // B: row-major [d][c] — float4 along n
            int nq = (slot & 31) * 4;
            int kk = slot >> 5;
            float4 w4 = *(const float4*)(W + (size_t)(k0 + kk) * INNER + c0 + nq);
            *(float4*)&Bs[kk][nq] = w4;
        }
        __syncthreads();

        #pragma unroll
        for (int s = 0; s < 4; s++) {
            const int kb = s * 8;
            uint32_t bh[4][2], bl[4][2];
            #pragma unroll
            for (int nt = 0; nt < 4; nt++) {
                int n = warp_n * 32 + nt * 8 + q;
                split_tf32(Bs[kb + r][n],     bh[nt][0], bl[nt][0]);
                split_tf32(Bs[kb + 4 + r][n], bh[nt][1], bl[nt][1]);
            }
            #pragma unroll
            for (int mt = 0; mt < 4; mt++) {
                int m = warp_m * 64 + mt * 16 + q;
                uint32_t ah[4], al[4];
                split_tf32(As[kb + r][m],         ah[0], al[0]);
                split_tf32(As[kb + r][m + 8],     ah[1], al[1]);
                split_tf32(As[kb + 4 + r][m],     ah[2], al[2]);
                split_tf32(As[kb + 4 + r][m + 8], ah[3], al[3]);
                #pragma unroll
                for (int nt = 0; nt < 4; nt++) {
                    mma_tf32(acc[mt][nt], ah, bh[nt]);
                    mma_tf32(acc[mt][nt], ah, bl[nt]);
                    mma_tf32(acc[mt][nt], al, bh[nt]);
                }
            }
        }
        __syncthreads();
    }

    // epilogue: transpose through smem, store [c][l] rows contiguous
    float* st = &As[0][0];   // 32 x 129 floats
    for (int p = 0; p < 4; p++) {
        if (warp_n == p) {
            #pragma unroll
            for (int mt = 0; mt < 4; mt++)
                #pragma unroll
                for (int nt = 0; nt < 4; nt++) {
                    int m = warp_m * 64 + mt * 16 + q;
                    int n = nt * 8 + 2 * r;
                    st[(n    ) * 129 + m    ] = acc[mt][nt][0];
                    st[(n + 1) * 129 + m    ] = acc[mt][nt][1];
                    st[(n    ) * 129 + m + 8] = acc[mt][nt][2];
                    st[(n + 1) * 129 + m + 8] = acc[mt][nt][3];
                }
        }
        __syncthreads();
        int row = tid >> 3;      // 0..31
        int cq  = tid & 7;       // 0..7
        int c   = c0 + p * 32 + row;
        float bb = bias[c];
        float* dst = Cb + (size_t)c * LL + l0;
        #pragma unroll
        for (int ii = 0; ii < 4; ii++) {
            int mq = cq + 8 * ii;
            float4 v = make_float4(st[row * 129 + mq * 4 + 0] + bb,
                                   st[row * 129 + mq * 4 + 1] + bb,
                                   st[row * 129 + mq * 4 + 2] + bb,
                                   st[row * 129 + mq * 4 + 3] + bb);
            *(float4*)(dst + mq * 4) = v;
        }
        __syncthreads();
    }
}

// ---------------- kernel 4: fused FFT conv ----------------
__global__ __launch_bounds__(NTH) void fftconv_kernel(
    const float* __restrict__ bias,
    const float* __restrict__ sw, const float* __restrict__ sb)
{
    extern __shared__ float2 smem_f2[];
    float2* data = smem_f2;
    float2* tw   = smem_f2 + N2;
    const int pr  = blockIdx.x;
    const int b   = blockIdx.y;
    const int tid = threadIdx.x;
    const int f0  = 2 * pr;
    const int f1  = 2 * pr + 1;

    build_twiddles(tw, tid);

    float v0[LL / NTH], v1[LL / NTH];
    {
        const float* r0 = d_proj + ((size_t)b * INNER + f0) * LL;
        const float* r1 = d_proj + ((size_t)b * INNER + f1) * LL;
        float a0 = sw[f0], a1 = sw[INNER + f0], a2 = sw[2 * INNER + f0], ab = sb[f0];
        float c0 = sw[f1], c1 = sw[INNER + f1], c2 = sw[2 * INNER + f1], cb = sb[f1];
        #pragma unroll
        for (int i = 0; i < LL / NTH; i++) {
            int l = tid + i * NTH;
            v0[i] = scval(r0, l, a0, a1, a2, ab);
            v1[i] = scval(r1, l, c0, c1, c2, cb);
        }
    }

    #pragma unroll 1
    for (int o = 0; o < ORDER; o++) {
        #pragma unroll
        for (int i = 0; i < LL / NTH; i++)
            data[tid + i * NTH] = make_float2(v0[i], v1[i]);
        #pragma unroll
        for (int i = LL / NTH; i < N2 / NTH; i++)
            data[tid + i * NTH] = make_float2(0.0f, 0.0f);
        __syncthreads();

        fft_fwd(data, tw, tid);

        const float2* hf0 = d_hf + (size_t)((o * NPAIR + pr) * 2 + 0) * N2;
        const float2* hf1 = d_hf + (size_t)((o * NPAIR + pr) * 2 + 1) * N2;
        #pragma unroll
        for (int i = 0; i < N2 / NTH; i++) {
            int p  = tid + i * NTH;
            int k  = rev14(p);
            int km = (N2 - k) & (N2 - 1);
            int pm = rev14(km);
            if (p <= pm) {
                float2 z1 = data[p];
                float2 z2 = data[pm];
                float2 V0 = make_float2(0.5f * (z1.x + z2.x),  0.5f * (z1.y - z2.y));
                float2 V1 = make_float2(0.5f * (z1.y + z2.y), -0.5f * (z1.x - z2.x));
                float2 H0 = hf0[p];
                float2 H1 = hf1[p];
                float2 Y0 = make_float2(V0.x * H0.x - V0.y * H0.y, V0.x * H0.y + V0.y * H0.x);
                float2 Y1 = make_float2(V1.x * H1.x - V1.y * H1.y, V1.x * H1.y + V1.y * H1.x);
                data[p]  = make_float2(Y0.x - Y1.y, Y0.y + Y1.x);
                data[pm] = make_float2(Y0.x + Y1.y, Y1.x - Y0.y);
            }
        }
        __syncthreads();

        fft_inv(data, tw, tid);

        float bs0 = bias[o * FF + f0];
        float bs1 = bias[o * FF + f1];
        const int g0c = (1 + o) * FF + f0;
        const int g1c = (1 + o) * FF + f1;
        const float* g0r = d_proj + ((size_t)b * INNER + g0c) * LL;
        const float* g1r = d_proj + ((size_t)b * INNER + g1c) * LL;
        float ga0 = sw[g0c], ga1 = sw[INNER + g0c], ga2 = sw[2 * INNER + g0c], gab = sb[g0c];
        float gc0 = sw[g1c], gc1 = sw[INNER + g1c], gc2 = sw[2 * INNER + g1c], gcb = sb[g1c];
        #pragma unroll
        for (int i = 0; i < LL / NTH; i++) {
            int l = tid + i * NTH;
            float2 y = data[l];
            float g0 = scval(g0r, l, ga0, ga1, ga2, gab);
            float g1 = scval(g1r, l, gc0, gc1, gc2, gcb);
            v0[i] = (y.x + v0[i] * bs0) * g0;
            v1[i] = (y.y + v1[i] * bs1) * g1;
        }
        __syncthreads();
    }
    float* dst0 = d_vout + ((size_t)b * FF + f0) * LL;
    float* dst1 = d_vout + ((size_t)b * FF + f1) * LL;
    #pragma unroll
    for (int i = 0; i < LL / NTH; i++) {
        dst0[tid + i * NTH] = v0[i];
        dst1[tid + i * NTH] = v1[i];
    }
}

// ---------------- kernel 5: output GEMM, tf32x3 tensor cores ----------------
// Y[b,l,d] = sum_f V[b][f][l]*W[f,d] + bias[d]   (A column-major from [f][l])
__global__ __launch_bounds__(256) void gemm_out_tc(
    const float* __restrict__ W, const float* __restrict__ bias,
    float* __restrict__ Y)
{
    __shared__ float As[32][132];   // [k(f)][m(l)]
    __shared__ float Bs[32][132];   // [k(f)][n(d)]
    const int b  = blockIdx.z;
    const int d0 = blockIdx.x * 128;
    const int l0 = blockIdx.y * 128;
    const float* Vb = d_vout + (size_t)b * FF * LL;
    float* Yb = Y + (size_t)b * LL * DD;

    const int tid    = threadIdx.x;
    const int wid    = tid >> 5;
    const int lane   = tid & 31;
    const int warp_m = wid >> 2;
    const int warp_n = wid & 3;
    const int q      = lane >> 2;
    const int r      = lane & 3;

    float acc[4][4][4];
    #pragma unroll
    for (int mt = 0; mt < 4; mt++)
        #pragma unroll
        for (int nt = 0; nt < 4; nt++)
            #pragma unroll
            for (int j = 0; j < 4; j++) acc[mt][nt][j] = 0.0f;

    for (int k0 = 0; k0 < FF; k0 += 32) {
        #pragma unroll
        for (int i = 0; i < 4; i++) {
            int slot = tid + i * 256;
            // A: column-major source [f][l] — float4 along m
            int mq = (slot & 31) * 4;
            int kk = slot >> 5;
            float4 v = *(const float4*)(Vb + (size_t)(k0 + kk) * LL + l0 + mq);
            *(float4*)&As[kk][mq] = v;
            // B: row-major [f][d] — float4 along n
            float4 w4 = *(const float4*)(W + (size_t)(k0 + kk) * DD + d0 + (slot & 31) * 4);
            *(float4*)&Bs[kk][(slot & 31) * 4] = w4;
        }
        __syncthreads();

        #pragma unroll
        for (int s = 0; s < 4; s++) {
            const int kb = s * 8;
            uint32_t bh[4][2], bl[4][2];
            #pragma unroll
            for (int nt = 0; nt < 4; nt++) {
                int n = warp_n * 32 + nt * 8 + q;
                split_tf32(Bs[kb + r][n],     bh[nt][0], bl[nt][0]);
                split_tf32(Bs[kb + 4 + r][n], bh[nt][1], bl[nt][1]);
            }
            #pragma unroll
            for (int mt = 0; mt < 4; mt++) {
                int m = warp_m * 64 + mt * 16 + q;
                uint32_t ah[4], al[4];
                split_tf32(As[kb + r][m],         ah[0], al[0]);
                split_tf32(As[kb + r][m + 8],     ah[1], al[1]);
                split_tf32(As[kb + 4 + r][m],     ah[2], al[2]);
                split_tf32(As[kb + 4 + r][m + 8], ah[3], al[3]);
                #pragma unroll
                for (int nt = 0; nt < 4; nt++) {
                    mma_tf32(acc[mt][nt], ah, bh[nt]);
                    mma_tf32(acc[mt][nt], ah, bl[nt]);
                    mma_tf32(acc[mt][nt], al, bh[nt]);
                }
            }
        }
        __syncthreads();
    }

    // epilogue: direct float2 stores (c0,c1) = consecutive d
    #pragma unroll
    for (int mt = 0; mt < 4; mt++) {
        #pragma unroll
        for (int nt = 0; nt < 4; nt++) {
            int n = d0 + warp_n * 32 + nt * 8 + 2 * r;
            float b0v = bias[n], b1v = bias[n + 1];
            int m = l0 + warp_m * 64 + mt * 16 + q;
            float2 o0 = make_float2(acc[mt][nt][0] + b0v, acc[mt][nt][1] + b1v);
            float2 o1 = make_float2(acc[mt][nt][2] + b0v, acc[mt][nt][3] + b1v);
            *(float2*)(Yb + (size_t)m * DD + n)       = o0;
            *(float2*)(Yb + (size_t)(m + 8) * DD + n) = o1;
        }
    }
}

// ---------------- launch ----------------
extern "C" void kernel_launch(void* const* d_in, const int* in_sizes, int n_in,
                              void* d_out, int out_size) {
    const float* u     = (const float*)d_in[0];
    const float* fw1   = (const float*)d_in[1];
    const float* fb1   = (const float*)d_in[2];
    const float* fw2   = (const float*)d_in[3];
    const float* fb2   = (const float*)d_in[4];
    const float* decay = (const float*)d_in[5];
    const float* bias  = (const float*)d_in[6];
    const float* ipw   = (const float*)d_in[7];
    const float* ipb   = (const float*)d_in[8];
    const float* sw    = (const float*)d_in[9];
    const float* sb    = (const float*)d_in[10];
    const float* ow    = (const float*)d_in[11];
    const float* ob    = (const float*)d_in[12];
    float* y = (float*)d_out;

    cudaFuncSetAttribute(hfft_kernel,    cudaFuncAttributeMaxDynamicSharedMemorySize, SMEM_FFT);
    cudaFuncSetAttribute(fftconv_kernel, cudaFuncAttributeMaxDynamicSharedMemorySize, SMEM_FFT);

    hfilter_kernel<<<N2 / 16, 256>>>(fw1, fb1, fw2, fb2, decay);
    hfft_kernel<<<ORDER * NPAIR, NTH, SMEM_FFT>>>();
    gemm_inproj_tc<<<dim3(INNER / 128, LL / 128, BB), 256>>>(u, ipw, ipb);
    fftconv_kernel<<<dim3(NPAIR, BB), NTH, SMEM_FFT>>>(bias, sw, sb);
    gemm_out_tc<<<dim3(DD / 128, LL / 128, BB), 256>>>(ow, ob, y);
}

// round 6
// speedup vs baseline: 2.1910x; 1.4801x over previous
#include <cuda_runtime.h>
#include <cuda_bf16.h>
#include <math.h>
#include <stdint.h>

// ---------------- problem constants ----------------
#define BB    2
#define LL    8192
#define N2    16384      // 2*L, FFT length = 4^7
#define DD    768
#define FF    768
#define ORDER 2
#define INNER 2304       // F*(ORDER+1)
#define NPAIR 384        // FF/2 channel pairs
#define FNTH  1024       // threads for FFT kernels
#define SMEM_FFT ((N2 + N2/4) * 8)   // 16384 float2 data + 4096 float2 twiddles = 163840 B

// ---------------- scratch (static device memory; no allocation) ----------------
__device__ float2 d_h2 [(size_t)ORDER * NPAIR * N2];        // filter pairs: .x = ch 2i, .y = ch 2i+1
__device__ float2 d_hf [(size_t)ORDER * NPAIR * 2 * N2];    // spectra [o][pair][ch][p] dr4 order, /n
__device__ float  d_proj[(size_t)BB * INNER * LL];          // in-proj output, [b][c][l]
__device__ float  d_vout[(size_t)BB * FF * LL];             // final v, [b][f][l]

// ---------------- complex helpers ----------------
__device__ __forceinline__ float2 cadd(float2 a, float2 b) { return make_float2(a.x + b.x, a.y + b.y); }
__device__ __forceinline__ float2 csub(float2 a, float2 b) { return make_float2(a.x - b.x, a.y - b.y); }
__device__ __forceinline__ float2 cmul(float2 a, float2 b) {
    return make_float2(a.x * b.x - a.y * b.y, a.x * b.y + a.y * b.x);
}
__device__ __forceinline__ float2 cmulc(float2 a, float2 b) {   // a * conj(b)
    return make_float2(a.x * b.x + a.y * b.y, a.y * b.x - a.x * b.y);
}

// base-4 digit reversal of a 14-bit index (involution)
__device__ __forceinline__ int dr4(int p) {
    unsigned r = __brev((unsigned)p) >> 18;                  // 14-bit bit reversal
    return (int)(((r & 0x2AAAu) >> 1) | ((r & 0x1555u) << 1)); // restore digit-internal order
}

// ---------------- radix-4 FFT (in-place, smem, 7 stages) ----------------
// forward: DIF, natural -> base4-digit-reversed order
__device__ __forceinline__ void fft4_fwd(float2* data, const float2* tw4, int tid) {
    #pragma unroll
    for (int t = 0; t < 7; t++) {
        const int lq = 12 - 2 * t;       // log2(Q)
        const int Q  = 1 << lq;
        #pragma unroll
        for (int u0 = 0; u0 < N2 / 4 / FNTH; u0++) {
            int u = tid + u0 * FNTH;
            int j = u & (Q - 1);
            int base = ((u >> lq) << (lq + 2)) + j;
            float2 a = data[base], b = data[base + Q];
            float2 c = data[base + 2 * Q], d = data[base + 3 * Q];
            float2 t0 = cadd(a, c), t1 = csub(a, c);
            float2 t2 = cadd(b, d), t3 = csub(b, d);
            float2 w1 = tw4[j << (2 * t)];
            float2 w2 = cmul(w1, w1);
            float2 w3 = cmul(w2, w1);
            data[base] = cadd(t0, t2);
            float2 X1 = make_float2(t1.x + t3.y, t1.y - t3.x);  // t1 - i*t3
            float2 X2 = csub(t0, t2);
            float2 X3 = make_float2(t1.x - t3.y, t1.y + t3.x);  // t1 + i*t3
            data[base + Q]     = cmul(X1, w1);
            data[base + 2 * Q] = cmul(X2, w2);
            data[base + 3 * Q] = cmul(X3, w3);
        }
        __syncthreads();
    }
}

// inverse: DIT, digit-reversed -> natural order, UNNORMALIZED, conjugate twiddles
__device__ __forceinline__ void fft4_inv(float2* data, const float2* tw4, int tid) {
    #pragma unroll
    for (int t = 0; t < 7; t++) {
        const int lq = 2 * t;            // log2(Q)
        const int Q  = 1 << lq;
        #pragma unroll
        for (int u0 = 0; u0 < N2 / 4 / FNTH; u0++) {
            int u = tid + u0 * FNTH;
            int j = u & (Q - 1);
            int base = ((u >> lq) << (lq + 2)) + j;
            float2 w1 = tw4[j << (12 - 2 * t)];
            float2 w2 = cmul(w1, w1);
            float2 w3 = cmul(w2, w1);
            float2 b0 = data[base];
            float2 b1 = cmulc(data[base + Q],     w1);
            float2 b2 = cmulc(data[base + 2 * Q], w2);
            float2 b3 = cmulc(data[base + 3 * Q], w3);
            float2 s0 = cadd(b0, b2), s1 = csub(b0, b2);
            float2 s2 = cadd(b1, b3), s3 = csub(b1, b3);
            data[base]         = cadd(s0, s2);
            data[base + Q]     = make_float2(s1.x - s3.y, s1.y + s3.x);  // s1 + i*s3
            data[base + 2 * Q] = csub(s0, s2);
            data[base + 3 * Q] = make_float2(s1.x + s3.y, s1.y - s3.x);  // s1 - i*s3
        }
        __syncthreads();
    }
}

__device__ __forceinline__ void build_twiddles4(float2* tw4, int tid) {
    #pragma unroll
    for (int i = 0; i < N2 / 4 / FNTH; i++) {
        int j = tid + i * FNTH;
        float x = -(float)j * (1.0f / 8192.0f);   // angle/pi = -2j/16384
        float s, c;
        sincospif(x, &s, &c);
        tw4[j] = make_float2(c, s);
    }
}

__device__ __forceinline__ float scval(const float* __restrict__ row, int l,
                                       float w0, float w1, float w2, float bb) {
    float acc = bb + w1 * row[l];
    if (l > 0)      acc += w0 * row[l - 1];
    if (l < LL - 1) acc += w2 * row[l + 1];
    return acc;
}

// ---------------- tf32x3 MMA helpers ----------------
__device__ __forceinline__ void split_tf32(float x, uint32_t& hi, uint32_t& lo) {
    uint32_t xb = __float_as_uint(x);
    hi = xb & 0xFFFFE000u;
    float lof = x - __uint_as_float(hi);
    lo = __float_as_uint(lof) & 0xFFFFE000u;
}

__device__ __forceinline__ void mma_tf32(float* c, const uint32_t* a, const uint32_t* b) {
    asm volatile(
        "mma.sync.aligned.m16n8k8.row.col.f32.tf32.tf32.f32 "
        "{%0,%1,%2,%3}, {%4,%5,%6,%7}, {%8,%9}, {%0,%1,%2,%3};"
        : "+f"(c[0]), "+f"(c[1]), "+f"(c[2]), "+f"(c[3])
        : "r"(a[0]), "r"(a[1]), "r"(a[2]), "r"(a[3]), "r"(b[0]), "r"(b[1]));
}

// ---------------- kernel 1: filter MLP + modulation (pair-interleaved output) ----
__global__ __launch_bounds__(256) void hfilter_kernel(
    const float* __restrict__ w1, const float* __restrict__ b1,
    const float* __restrict__ w2, const float* __restrict__ b2,
    const float* __restrict__ decay)
{
    __shared__ float hid[16][64];
    const int p0  = blockIdx.x * 16;
    const int tid = threadIdx.x;

    for (int idx = tid; idx < 16 * 64; idx += 256) {
        int pp = idx >> 6;
        int u  = idx & 63;
        int p  = p0 + pp;
        float off = (p < LL) ? (float)p : (float)(p - N2);
        float t[9];
        t[0] = off * (1.0f / 8192.0f);
        const float step = (8192.0f - 4.0f) / 3.0f;
        #pragma unroll
        for (int i = 0; i < 4; i++) {
            float period = 4.0f + step * (float)i;
            float fr = 6.28318530717958647692f / period;
            float ph = off * fr;
            t[1 + i] = cosf(ph);
            t[5 + i] = sinf(ph);
        }
        float a = b1[u];
        #pragma unroll
        for (int k = 0; k < 9; k++) a += t[k] * w1[k * 64 + u];
        hid[pp][u] = sinf(a);
    }
    __syncthreads();

    for (int oc = tid; oc < ORDER * FF; oc += 256) {
        float acc[16];
        float bv = b2[oc];
        #pragma unroll
        for (int pp = 0; pp < 16; pp++) acc[pp] = bv;
        for (int k = 0; k < 64; k++) {
            float wv = w2[k * (ORDER * FF) + oc];
            #pragma unroll
            for (int pp = 0; pp < 16; pp++) acc[pp] += hid[pp][k] * wv;
        }
        float dec = fabsf(decay[oc]);
        int o = oc / FF, f = oc - o * FF;
        float* dst = (float*)(d_h2 + ((size_t)(o * NPAIR + (f >> 1))) * N2 + p0) + (f & 1);
        #pragma unroll
        for (int pp = 0; pp < 16; pp++) {
            int p = p0 + pp;
            float mod = (p < LL) ? (float)p * (1.0f / 8191.0f)
                                 : (float)(N2 - 1 - p) * (1.0f / 8191.0f);
            dst[2 * pp] = acc[pp] * expf(-mod * dec);
        }
    }
}

// ---------------- kernel 2: paired filter FFT (radix-4) ----------------
__global__ __launch_bounds__(FNTH) void hfft_kernel() {
    extern __shared__ float2 smem_f2[];
    float2* data = smem_f2;
    float2* tw4  = smem_f2 + N2;
    const int cp  = blockIdx.x;
    const int tid = threadIdx.x;

    build_twiddles4(tw4, tid);
    const float2* src = d_h2 + (size_t)cp * N2;
    #pragma unroll
    for (int i = 0; i < N2 / FNTH; i++) {
        int idx = tid + i * FNTH;
        data[idx] = src[idx];
    }
    __syncthreads();
    fft4_fwd(data, tw4, tid);

    const float s = 0.5f / (float)N2;
    float2* hf0 = d_hf + (size_t)(cp * 2 + 0) * N2;
    float2* hf1 = d_hf + (size_t)(cp * 2 + 1) * N2;
    #pragma unroll
    for (int i = 0; i < N2 / FNTH; i++) {
        int p  = tid + i * FNTH;
        int k  = dr4(p);
        int km = (N2 - k) & (N2 - 1);
        int pm = dr4(km);
        if (p <= pm) {
            float2 z1 = data[p];
            float2 z2 = data[pm];
            float2 H0 = make_float2(s * (z1.x + z2.x),  s * (z1.y - z2.y));
            float2 H1 = make_float2(s * (z1.y + z2.y), -s * (z1.x - z2.x));
            hf0[p]  = H0;
            hf1[p]  = H1;
            hf0[pm] = make_float2(H0.x, -H0.y);
            hf1[pm] = make_float2(H1.x, -H1.y);
        }
    }
}

// ---------------- kernel 3: in-projection GEMM, tf32x3 tensor cores ----------------
// C[b,c,l] = sum_d U[b,l,d]*W[d,c] + bias[c]  (output transposed [c][l])
__global__ __launch_bounds__(256) void gemm_inproj_tc(
    const float* __restrict__ U, const float* __restrict__ W,
    const float* __restrict__ bias)
{
    __shared__ float As[32][132];   // [k][m(l)]
    __shared__ float Bs[32][132];   // [k][n(c)]
    const int b  = blockIdx.z;
    const int c0 = blockIdx.x * 128;
    const int l0 = blockIdx.y * 128;
    const float* Ub = U + (size_t)b * LL * DD;
    float* Cb = d_proj + (size_t)b * INNER * LL;

    const int tid    = threadIdx.x;
    const int wid    = tid >> 5;
    const int lane   = tid & 31;
    const int warp_m = wid >> 2;    // 0..1
    const int warp_n = wid & 3;     // 0..3
    const int q      = lane >> 2;   // 0..7
    const int r      = lane & 3;    // 0..3

    float acc[4][4][4];
    #pragma unroll
    for (int mt = 0; mt < 4; mt++)
        #pragma unroll
        for (int nt = 0; nt < 4; nt++)
            #pragma unroll
            for (int j = 0; j < 4; j++) acc[mt][nt][j] = 0.0f;

    for (int k0 = 0; k0 < DD; k0 += 32) {
        #pragma unroll
        for (int i = 0; i < 4; i++) {
            int slot = tid + i * 256;
            int m  = slot >> 3;
            int kq = (slot & 7) * 4;
            float4 v = *(const float4*)(Ub + (size_t)(l0 + m) * DD + k0 + kq);
            As[kq + 0][m] = v.x;
            As[kq + 1][m] = v.y;
            As[kq + 2][m] = v.z;
            As[kq + 3][m] = v.w;
            int nq = (slot & 31) * 4;
            int kk = slot >> 5;
            float4 w4 = *(const float4*)(W + (size_t)(k0 + kk) * INNER + c0 + nq);
            *(float4*)&Bs[kk][nq] = w4;
        }
        __syncthreads();

        #pragma unroll
        for (int s = 0; s < 4; s++) {
            const int kb = s * 8;
            uint32_t bh[4][2], bl[4][2];
            #pragma unroll
            for (int nt = 0; nt < 4; nt++) {
                int n = warp_n * 32 + nt * 8 + q;
                split_tf32(Bs[kb + r][n],     bh[nt][0], bl[nt][0]);
                split_tf32(Bs[kb + 4 + r][n], bh[nt][1], bl[nt][1]);
            }
            #pragma unroll
            for (int mt = 0; mt < 4; mt++) {
                int m = warp_m * 64 + mt * 16 + q;
                uint32_t ah[4], al[4];
                split_tf32(As[kb + r][m],         ah[0], al[0]);
                split_tf32(As[kb + r][m + 8],     ah[1], al[1]);
                split_tf32(As[kb + 4 + r][m],     ah[2], al[2]);
                split_tf32(As[kb + 4 + r][m + 8], ah[3], al[3]);
                #pragma unroll
                for (int nt = 0; nt < 4; nt++) {
                    mma_tf32(acc[mt][nt], ah, bh[nt]);
                    mma_tf32(acc[mt][nt], ah, bl[nt]);
                    mma_tf32(acc[mt][nt], al, bh[nt]);
                }
            }
        }
        __syncthreads();
    }

    // epilogue: transpose through smem, store [c][l] rows contiguous
    float* st = &As[0][0];   // 32 x 129 floats
    for (int p = 0; p < 4; p++) {
        if (warp_n == p) {
            #pragma unroll
            for (int mt = 0; mt < 4; mt++)
                #pragma unroll
                for (int nt = 0; nt < 4; nt++) {
                    int m = warp_m * 64 + mt * 16 + q;
                    int n = nt * 8 + 2 * r;
                    st[(n    ) * 129 + m    ] = acc[mt][nt][0];
                    st[(n + 1) * 129 + m    ] = acc[mt][nt][1];
                    st[(n    ) * 129 + m + 8] = acc[mt][nt][2];
                    st[(n + 1) * 129 + m + 8] = acc[mt][nt][3];
                }
        }
        __syncthreads();
        int row = tid >> 3;      // 0..31
        int cq  = tid & 7;       // 0..7
        int c   = c0 + p * 32 + row;
        float bb = bias[c];
        float* dst = Cb + (size_t)c * LL + l0;
        #pragma unroll
        for (int ii = 0; ii < 4; ii++) {
            int mq = cq + 8 * ii;
            float4 v = make_float4(st[row * 129 + mq * 4 + 0] + bb,
                                   st[row * 129 + mq * 4 + 1] + bb,
                                   st[row * 129 + mq * 4 + 2] + bb,
                                   st[row * 129 + mq * 4 + 3] + bb);
            *(float4*)(dst + mq * 4) = v;
        }
        __syncthreads();
    }
}

// ---------------- kernel 4: fused FFT conv (radix-4, 2 channels/block) ----------------
__global__ __launch_bounds__(FNTH) void fftconv_kernel(
    const float* __restrict__ bias,
    const float* __restrict__ sw, const float* __restrict__ sb)
{
    extern __shared__ float2 smem_f2[];
    float2* data = smem_f2;
    float2* tw4  = smem_f2 + N2;
    const int pr  = blockIdx.x;
    const int b   = blockIdx.y;
    const int tid = threadIdx.x;
    const int f0  = 2 * pr;
    const int f1  = 2 * pr + 1;

    build_twiddles4(tw4, tid);

    float v0[LL / FNTH], v1[LL / FNTH];
    {
        const float* r0 = d_proj + ((size_t)b * INNER + f0) * LL;
        const float* r1 = d_proj + ((size_t)b * INNER + f1) * LL;
        float a0 = sw[f0], a1 = sw[INNER + f0], a2 = sw[2 * INNER + f0], ab = sb[f0];
        float c0 = sw[f1], c1 = sw[INNER + f1], c2 = sw[2 * INNER + f1], cb = sb[f1];
        #pragma unroll
        for (int i = 0; i < LL / FNTH; i++) {
            int l = tid + i * FNTH;
            v0[i] = scval(r0, l, a0, a1, a2, ab);
            v1[i] = scval(r1, l, c0, c1, c2, cb);
        }
    }

    #pragma unroll 1
    for (int o = 0; o < ORDER; o++) {
        #pragma unroll
        for (int i = 0; i < LL / FNTH; i++)
            data[tid + i * FNTH] = make_float2(v0[i], v1[i]);
        #pragma unroll
        for (int i = LL / FNTH; i < N2 / FNTH; i++)
            data[tid + i * FNTH] = make_float2(0.0f, 0.0f);
        __syncthreads();

        fft4_fwd(data, tw4, tid);

        const float2* hf0 = d_hf + (size_t)((o * NPAIR + pr) * 2 + 0) * N2;
        const float2* hf1 = d_hf + (size_t)((o * NPAIR + pr) * 2 + 1) * N2;
        #pragma unroll
        for (int i = 0; i < N2 / FNTH; i++) {
            int p  = tid + i * FNTH;
            int k  = dr4(p);
            int km = (N2 - k) & (N2 - 1);
            int pm = dr4(km);
            if (p <= pm) {
                float2 z1 = data[p];
                float2 z2 = data[pm];
                float2 V0 = make_float2(0.5f * (z1.x + z2.x),  0.5f * (z1.y - z2.y));
                float2 V1 = make_float2(0.5f * (z1.y + z2.y), -0.5f * (z1.x - z2.x));
                float2 H0 = hf0[p];
                float2 H1 = hf1[p];
                float2 Y0 = cmul(V0, H0);
                float2 Y1 = cmul(V1, H1);
                data[p]  = make_float2(Y0.x - Y1.y, Y0.y + Y1.x);
                data[pm] = make_float2(Y0.x + Y1.y, Y1.x - Y0.y);
            }
        }
        __syncthreads();

        fft4_inv(data, tw4, tid);

        float bs0 = bias[o * FF + f0];
        float bs1 = bias[o * FF + f1];
        const int g0c = (1 + o) * FF + f0;
        const int g1c = (1 + o) * FF + f1;
        const float* g0r = d_proj + ((size_t)b * INNER + g0c) * LL;
        const float* g1r = d_proj + ((size_t)b * INNER + g1c) * LL;
        float ga0 = sw[g0c], ga1 = sw[INNER + g0c], ga2 = sw[2 * INNER + g0c], gab = sb[g0c];
        float gc0 = sw[g1c], gc1 = sw[INNER + g1c], gc2 = sw[2 * INNER + g1c], gcb = sb[g1c];
        #pragma unroll
        for (int i = 0; i < LL / FNTH; i++) {
            int l = tid + i * FNTH;
            float2 y = data[l];
            float g0 = scval(g0r, l, ga0, ga1, ga2, gab);
            float g1 = scval(g1r, l, gc0, gc1, gc2, gcb);
            v0[i] = (y.x + v0[i] * bs0) * g0;
            v1[i] = (y.y + v1[i] * bs1) * g1;
        }
        __syncthreads();
    }
    float* dst0 = d_vout + ((size_t)b * FF + f0) * LL;
    float* dst1 = d_vout + ((size_t)b * FF + f1) * LL;
    #pragma unroll
    for (int i = 0; i < LL / FNTH; i++) {
        dst0[tid + i * FNTH] = v0[i];
        dst1[tid + i * FNTH] = v1[i];
    }
}

// ---------------- kernel 5: output GEMM, tf32x3 tensor cores ----------------
// Y[b,l,d] = sum_f V[b][f][l]*W[f,d] + bias[d]
__global__ __launch_bounds__(256) void gemm_out_tc(
    const float* __restrict__ W, const float* __restrict__ bias,
    float* __restrict__ Y)
{
    __shared__ float As[32][132];   // [k(f)][m(l)]
    __shared__ float Bs[32][132];   // [k(f)][n(d)]
    const int b  = blockIdx.z;
    const int d0 = blockIdx.x * 128;
    const int l0 = blockIdx.y * 128;
    const float* Vb = d_vout + (size_t)b * FF * LL;
    float* Yb = Y + (size_t)b * LL * DD;

    const int tid    = threadIdx.x;
    const int wid    = tid >> 5;
    const int lane   = tid & 31;
    const int warp_m = wid >> 2;
    const int warp_n = wid & 3;
    const int q      = lane >> 2;
    const int r      = lane & 3;

    float acc[4][4][4];
    #pragma unroll
    for (int mt = 0; mt < 4; mt++)
        #pragma unroll
        for (int nt = 0; nt < 4; nt++)
            #pragma unroll
            for (int j = 0; j < 4; j++) acc[mt][nt][j] = 0.0f;

    for (int k0 = 0; k0 < FF; k0 += 32) {
        #pragma unroll
        for (int i = 0; i < 4; i++) {
            int slot = tid + i * 256;
            int mq = (slot & 31) * 4;
            int kk = slot >> 5;
            float4 v = *(const float4*)(Vb + (size_t)(k0 + kk) * LL + l0 + mq);
            *(float4*)&As[kk][mq] = v;
            float4 w4 = *(const float4*)(W + (size_t)(k0 + kk) * DD + d0 + (slot & 31) * 4);
            *(float4*)&Bs[kk][(slot & 31) * 4] = w4;
        }
        __syncthreads();

        #pragma unroll
        for (int s = 0; s < 4; s++) {
            const int kb = s * 8;
            uint32_t bh[4][2], bl[4][2];
            #pragma unroll
            for (int nt = 0; nt < 4; nt++) {
                int n = warp_n * 32 + nt * 8 + q;
                split_tf32(Bs[kb + r][n],     bh[nt][0], bl[nt][0]);
                split_tf32(Bs[kb + 4 + r][n], bh[nt][1], bl[nt][1]);
            }
            #pragma unroll
            for (int mt = 0; mt < 4; mt++) {
                int m = warp_m * 64 + mt * 16 + q;
                uint32_t ah[4], al[4];
                split_tf32(As[kb + r][m],         ah[0], al[0]);
                split_tf32(As[kb + r][m + 8],     ah[1], al[1]);
                split_tf32(As[kb + 4 + r][m],     ah[2], al[2]);
                split_tf32(As[kb + 4 + r][m + 8], ah[3], al[3]);
                #pragma unroll
                for (int nt = 0; nt < 4; nt++) {
                    mma_tf32(acc[mt][nt], ah, bh[nt]);
                    mma_tf32(acc[mt][nt], ah, bl[nt]);
                    mma_tf32(acc[mt][nt], al, bh[nt]);
                }
            }
        }
        __syncthreads();
    }

    #pragma unroll
    for (int mt = 0; mt < 4; mt++) {
        #pragma unroll
        for (int nt = 0; nt < 4; nt++) {
            int n = d0 + warp_n * 32 + nt * 8 + 2 * r;
            float b0v = bias[n], b1v = bias[n + 1];
            int m = l0 + warp_m * 64 + mt * 16 + q;
            float2 o0 = make_float2(acc[mt][nt][0] + b0v, acc[mt][nt][1] + b1v);
            float2 o1 = make_float2(acc[mt][nt][2] + b0v, acc[mt][nt][3] + b1v);
            *(float2*)(Yb + (size_t)m * DD + n)       = o0;
            *(float2*)(Yb + (size_t)(m + 8) * DD + n) = o1;
        }
    }
}

// ---------------- launch ----------------
extern "C" void kernel_launch(void* const* d_in, const int* in_sizes, int n_in,
                              void* d_out, int out_size) {
    const float* u     = (const float*)d_in[0];
    const float* fw1   = (const float*)d_in[1];
    const float* fb1   = (const float*)d_in[2];
    const float* fw2   = (const float*)d_in[3];
    const float* fb2   = (const float*)d_in[4];
    const float* decay = (const float*)d_in[5];
    const float* bias  = (const float*)d_in[6];
    const float* ipw   = (const float*)d_in[7];
    const float* ipb   = (const float*)d_in[8];
    const float* sw    = (const float*)d_in[9];
    const float* sb    = (const float*)d_in[10];
    const float* ow    = (const float*)d_in[11];
    const float* ob    = (const float*)d_in[12];
    float* y = (float*)d_out;

    cudaFuncSetAttribute(hfft_kernel,    cudaFuncAttributeMaxDynamicSharedMemorySize, SMEM_FFT);
    cudaFuncSetAttribute(fftconv_kernel, cudaFuncAttributeMaxDynamicSharedMemorySize, SMEM_FFT);

    hfilter_kernel<<<N2 / 16, 256>>>(fw1, fb1, fw2, fb2, decay);
    hfft_kernel<<<ORDER * NPAIR, FNTH, SMEM_FFT>>>();
    gemm_inproj_tc<<<dim3(INNER / 128, LL / 128, BB), 256>>>(u, ipw, ipb);
    fftconv_kernel<<<dim3(NPAIR, BB), FNTH, SMEM_FFT>>>(bias, sw, sb);
    gemm_out_tc<<<dim3(DD / 128, LL / 128, BB), 256>>>(ow, ob, y);
}